// round 1
// baseline (speedup 1.0000x reference)
#include <cuda_runtime.h>
#include <math.h>

// ---------------------------------------------------------------------------
// Problem constants (B=2, S=2048, D=1024, H=16, Hd=64)
// ---------------------------------------------------------------------------
#define AB 2
#define AS 2048
#define AD 1024
#define AH 16
#define AHD 64

// Scratch: q, k, v, attn-out  (each B*S*D floats = 16.8 MB)
__device__ float g_q[AB * AS * AD];
__device__ float g_k[AB * AS * AD];
__device__ float g_v[AB * AS * AD];
__device__ float g_attn[AB * AS * AD];

// ---------------------------------------------------------------------------
// GEMM:  C[M,N] = A[M,K] @ W[N,K]^T + bias[N]
// 128x128x16 tiles, 256 threads, 8x8 per-thread micro-tile.
// Smem stored transposed ([k][m], pad +4) so inner-loop reads are LDS.128.
// ---------------------------------------------------------------------------
#define GBM 128
#define GBN 128
#define GBK 16
#define GLD (GBM + 4)   // 132: float4-aligned rows, cheap write conflicts

__global__ __launch_bounds__(256) void gemm_bias_kernel(
    const float* __restrict__ A, const float* __restrict__ W,
    const float* __restrict__ bias, float* __restrict__ C,
    int M, int N, int K)
{
    __shared__ __align__(16) float As[GBK][GLD];
    __shared__ __align__(16) float Ws[GBK][GLD];

    const int tid = threadIdx.x;
    const int tx = tid & 15;      // 0..15 -> N micro
    const int ty = tid >> 4;      // 0..15 -> M micro
    const int m0 = blockIdx.y * GBM;
    const int n0 = blockIdx.x * GBN;

    const int lm = tid >> 2;          // 0..63
    const int lk = (tid & 3) * 4;     // 0,4,8,12

    float acc[8][8] = {};

    for (int k0 = 0; k0 < K; k0 += GBK) {
        // load A and W tiles (float4 gmem), store transposed into smem
        #pragma unroll
        for (int half = 0; half < 2; half++) {
            const int m = lm + half * 64;
            float4 av = *(const float4*)&A[(size_t)(m0 + m) * K + k0 + lk];
            float4 wv = *(const float4*)&W[(size_t)(n0 + m) * K + k0 + lk];
            As[lk + 0][m] = av.x; As[lk + 1][m] = av.y;
            As[lk + 2][m] = av.z; As[lk + 3][m] = av.w;
            Ws[lk + 0][m] = wv.x; Ws[lk + 1][m] = wv.y;
            Ws[lk + 2][m] = wv.z; Ws[lk + 3][m] = wv.w;
        }
        __syncthreads();

        #pragma unroll
        for (int kk = 0; kk < GBK; kk++) {
            float a[8], b[8];
            *(float4*)&a[0] = *(const float4*)&As[kk][8 * ty];
            *(float4*)&a[4] = *(const float4*)&As[kk][8 * ty + 4];
            *(float4*)&b[0] = *(const float4*)&Ws[kk][8 * tx];
            *(float4*)&b[4] = *(const float4*)&Ws[kk][8 * tx + 4];
            #pragma unroll
            for (int i = 0; i < 8; i++)
                #pragma unroll
                for (int j = 0; j < 8; j++)
                    acc[i][j] = fmaf(a[i], b[j], acc[i][j]);
        }
        __syncthreads();
    }

    #pragma unroll
    for (int i = 0; i < 8; i++) {
        const size_t row = (size_t)(m0 + 8 * ty + i) * N;
        #pragma unroll
        for (int j = 0; j < 8; j++) {
            const int n = n0 + 8 * tx + j;
            C[row + n] = acc[i][j] + bias[n];
        }
    }
}

// ---------------------------------------------------------------------------
// Flash attention (causal), fp32, online softmax.
// Per block: one (batch, head), 64 query rows. Iterate key tiles kt <= qt.
// 256 threads (16x16), each owns a 4x4 micro-tile of the 64x64 score tile
// (rows = queries, cols = keys) and a 4x4 micro-tile of the 64x64 output
// tile (rows = queries, cols = head dims).
// ---------------------------------------------------------------------------
#define LDP 65   // smem row stride (floats): 2-way conflicts worst case

__global__ __launch_bounds__(256) void flash_attn_kernel(
    const float* __restrict__ q, const float* __restrict__ k,
    const float* __restrict__ v, float* __restrict__ o)
{
    extern __shared__ float smem[];
    float* Qs  = smem;                 // [64][LDP]  query tile
    float* KVs = smem + 64 * LDP;      // [64][LDP]  key tile, then value tile
    float* Ps  = smem + 2 * 64 * LDP;  // [64][LDP]  exp-score tile

    const int tid = threadIdx.x;
    const int tx = tid & 15;
    const int ty = tid >> 4;
    const int qt = blockIdx.x;                 // query tile index
    const int b  = blockIdx.y / AH;
    const int h  = blockIdx.y % AH;

    const size_t base = (size_t)b * AS * AD + (size_t)h * AHD;
    const float* qb = q + base;
    const float* kb = k + base;
    const float* vb = v + base;
    float*       ob = o + base;

    const int q0 = qt * 64;

    // load Q tile
    for (int i = tid; i < 64 * 64; i += 256) {
        const int r = i >> 6, c = i & 63;
        Qs[r * LDP + c] = qb[(size_t)(q0 + r) * AD + c];
    }

    float m_i[4], l_i[4], acc[4][4] = {};
    #pragma unroll
    for (int i = 0; i < 4; i++) { m_i[i] = -1e30f; l_i[i] = 0.0f; }

    const float scale = 0.125f;   // 1/sqrt(64)

    for (int kt = 0; kt <= qt; kt++) {
        const int k0 = kt * 64;

        __syncthreads();   // prev iteration done reading KVs/Ps; Qs ready (1st iter)

        // load K tile
        for (int i = tid; i < 64 * 64; i += 256) {
            const int r = i >> 6, c = i & 63;
            KVs[r * LDP + c] = kb[(size_t)(k0 + r) * AD + c];
        }
        __syncthreads();

        // scores: s[i][j] = Q[q0+4ty+i] . K[k0+4tx+j]
        float s[4][4] = {};
        #pragma unroll 8
        for (int kk = 0; kk < 64; kk++) {
            float a[4], bb[4];
            #pragma unroll
            for (int i = 0; i < 4; i++) a[i]  = Qs[(4 * ty + i) * LDP + kk];
            #pragma unroll
            for (int j = 0; j < 4; j++) bb[j] = KVs[(4 * tx + j) * LDP + kk];
            #pragma unroll
            for (int i = 0; i < 4; i++)
                #pragma unroll
                for (int j = 0; j < 4; j++)
                    s[i][j] = fmaf(a[i], bb[j], s[i][j]);
        }
        __syncthreads();   // everyone done reading K tile

        // load V tile (overwrites KVs)
        for (int i = tid; i < 64 * 64; i += 256) {
            const int r = i >> 6, c = i & 63;
            KVs[r * LDP + c] = vb[(size_t)(k0 + r) * AD + c];
        }

        // online softmax (registers + shuffles; Ps written below)
        const bool diag = (kt == qt);
        #pragma unroll
        for (int i = 0; i < 4; i++) {
            const int qrow = q0 + 4 * ty + i;
            float sv[4];
            #pragma unroll
            for (int j = 0; j < 4; j++) {
                float val = s[i][j] * scale;
                if (diag && (k0 + 4 * tx + j > qrow)) val = -1e30f;
                sv[j] = val;
            }
            float mx = fmaxf(fmaxf(sv[0], sv[1]), fmaxf(sv[2], sv[3]));
            #pragma unroll
            for (int off = 8; off >= 1; off >>= 1)
                mx = fmaxf(mx, __shfl_xor_sync(0xffffffffu, mx, off));
            const float mnew  = fmaxf(m_i[i], mx);
            const float alpha = __expf(m_i[i] - mnew);
            float rs = 0.0f;
            #pragma unroll
            for (int j = 0; j < 4; j++) {
                const float p = __expf(sv[j] - mnew);
                Ps[(4 * ty + i) * LDP + 4 * tx + j] = p;
                rs += p;
            }
            #pragma unroll
            for (int off = 8; off >= 1; off >>= 1)
                rs += __shfl_xor_sync(0xffffffffu, rs, off);
            l_i[i] = l_i[i] * alpha + rs;
            m_i[i] = mnew;
            #pragma unroll
            for (int j = 0; j < 4; j++) acc[i][j] *= alpha;
        }
        __syncthreads();   // V loaded + Ps written

        // O += P @ V  : acc[i][j] += sum_kk Ps[4ty+i][kk] * V[kk][4tx+j]
        #pragma unroll 4
        for (int kk = 0; kk < 64; kk++) {
            float a[4], vv[4];
            #pragma unroll
            for (int i = 0; i < 4; i++) a[i]  = Ps[(4 * ty + i) * LDP + kk];
            #pragma unroll
            for (int j = 0; j < 4; j++) vv[j] = KVs[kk * LDP + 4 * tx + j];
            #pragma unroll
            for (int i = 0; i < 4; i++)
                #pragma unroll
                for (int j = 0; j < 4; j++)
                    acc[i][j] = fmaf(a[i], vv[j], acc[i][j]);
        }
    }

    // epilogue: normalize by l and write out in [B,S,H,Hd] layout
    #pragma unroll
    for (int i = 0; i < 4; i++) {
        const float inv = 1.0f / l_i[i];
        const size_t row = (size_t)(q0 + 4 * ty + i) * AD;
        #pragma unroll
        for (int j = 0; j < 4; j++)
            ob[row + 4 * tx + j] = acc[i][j] * inv;
    }
}

// ---------------------------------------------------------------------------
// Launch
// ---------------------------------------------------------------------------
extern "C" void kernel_launch(void* const* d_in, const int* in_sizes, int n_in,
                              void* d_out, int out_size)
{
    const float* x  = (const float*)d_in[0];
    const float* wq = (const float*)d_in[1];
    const float* bq = (const float*)d_in[2];
    const float* wk = (const float*)d_in[3];
    const float* bk = (const float*)d_in[4];
    const float* wv = (const float*)d_in[5];
    const float* bv = (const float*)d_in[6];
    const float* wo = (const float*)d_in[7];
    const float* bo = (const float*)d_in[8];
    float* out = (float*)d_out;

    const int M = AB * AS;   // 4096
    const int N = AD;        // 1024
    const int K = AD;        // 1024

    float *gq, *gk, *gv, *ga;
    cudaGetSymbolAddress((void**)&gq, g_q);
    cudaGetSymbolAddress((void**)&gk, g_k);
    cudaGetSymbolAddress((void**)&gv, g_v);
    cudaGetSymbolAddress((void**)&ga, g_attn);

    dim3 gb(N / GBN, M / GBM);   // (8, 32)

    gemm_bias_kernel<<<gb, 256>>>(x, wq, bq, gq, M, N, K);
    gemm_bias_kernel<<<gb, 256>>>(x, wk, bk, gk, M, N, K);
    gemm_bias_kernel<<<gb, 256>>>(x, wv, bv, gv, M, N, K);

    const size_t shm = (size_t)3 * 64 * LDP * sizeof(float);  // 49920 B
    cudaFuncSetAttribute(flash_attn_kernel,
                         cudaFuncAttributeMaxDynamicSharedMemorySize, (int)shm);
    flash_attn_kernel<<<dim3(AS / 64, AB * AH), 256, shm>>>(gq, gk, gv, ga);

    gemm_bias_kernel<<<gb, 256>>>(ga, wo, bo, out, M, N, K);
}

// round 6
// speedup vs baseline: 1.3222x; 1.3222x over previous
#include <cuda_runtime.h>
#include <cuda_bf16.h>
#include <cstdint>
#include <math.h>

// ---------------------------------------------------------------------------
// Problem constants (B=2, S=2048, D=1024, H=16, Hd=64)
// ---------------------------------------------------------------------------
#define AB 2
#define AS 2048
#define AD 1024
#define AH 16
#define AHD 64
#define AM (AB * AS)          // 4096 rows

// fp32 scratch
__device__ __align__(256) float g_q[AM * AD];
__device__ __align__(256) float g_k[AM * AD];
__device__ __align__(256) float g_v[AM * AD];
__device__ __align__(256) float g_attn[AM * AD];

// bf16 hi/lo split scratch
__device__ __align__(256) __nv_bfloat16 g_xhi[AM * AD];
__device__ __align__(256) __nv_bfloat16 g_xlo[AM * AD];
__device__ __align__(256) __nv_bfloat16 g_whi[4][AD * AD];   // q,k,v,o weights
__device__ __align__(256) __nv_bfloat16 g_wlo[4][AD * AD];
__device__ __align__(256) __nv_bfloat16 g_ahi[AM * AD];
__device__ __align__(256) __nv_bfloat16 g_alo[AM * AD];

// ---------------------------------------------------------------------------
// mma.sync helpers (sm_80+ path; works on plain sm_103 ptxas target)
// ---------------------------------------------------------------------------
__device__ __forceinline__ uint32_t smem_u32(const void* p) {
    return (uint32_t)__cvta_generic_to_shared(p);
}

__device__ __forceinline__ void ldmatrix_x4(uint32_t* r, uint32_t addr) {
    asm volatile("ldmatrix.sync.aligned.m8n8.x4.shared.b16 {%0,%1,%2,%3}, [%4];"
        : "=r"(r[0]), "=r"(r[1]), "=r"(r[2]), "=r"(r[3]) : "r"(addr));
}

__device__ __forceinline__ void mma_bf16(float* c, const uint32_t* a, const uint32_t* b) {
    asm volatile(
        "mma.sync.aligned.m16n8k16.row.col.f32.bf16.bf16.f32 "
        "{%0,%1,%2,%3}, {%4,%5,%6,%7}, {%8,%9}, {%0,%1,%2,%3};"
        : "+f"(c[0]), "+f"(c[1]), "+f"(c[2]), "+f"(c[3])
        : "r"(a[0]), "r"(a[1]), "r"(a[2]), "r"(a[3]), "r"(b[0]), "r"(b[1]));
}

// ---------------------------------------------------------------------------
// fp32 -> bf16 hi/lo split (vectorized x4)
// ---------------------------------------------------------------------------
__global__ __launch_bounds__(256) void split_kernel(
    const float* __restrict__ src, __nv_bfloat16* __restrict__ hi,
    __nv_bfloat16* __restrict__ lo, int n4)
{
    int i = blockIdx.x * blockDim.x + threadIdx.x;
    if (i >= n4) return;
    float4 v = ((const float4*)src)[i];
    __nv_bfloat16 h0 = __float2bfloat16(v.x);
    __nv_bfloat16 h1 = __float2bfloat16(v.y);
    __nv_bfloat16 h2 = __float2bfloat16(v.z);
    __nv_bfloat16 h3 = __float2bfloat16(v.w);
    __nv_bfloat162 hp0; hp0.x = h0; hp0.y = h1;
    __nv_bfloat162 hp1; hp1.x = h2; hp1.y = h3;
    ((__nv_bfloat162*)hi)[2 * i]     = hp0;
    ((__nv_bfloat162*)hi)[2 * i + 1] = hp1;
    __nv_bfloat162 lp0, lp1;
    lp0.x = __float2bfloat16(v.x - __bfloat162float(h0));
    lp0.y = __float2bfloat16(v.y - __bfloat162float(h1));
    lp1.x = __float2bfloat16(v.z - __bfloat162float(h2));
    lp1.y = __float2bfloat16(v.w - __bfloat162float(h3));
    ((__nv_bfloat162*)lo)[2 * i]     = lp0;
    ((__nv_bfloat162*)lo)[2 * i + 1] = lp1;
}

// ---------------------------------------------------------------------------
// bf16 split GEMM via mma.sync:  C[M,1024] = A @ W^T + bias
//   C = Ahi*Whi + Ahi*Wlo + Alo*Whi   (fp32 accumulate)
// CTA: 128x128 tile, BK=32. 256 threads = 8 warps (2 m x 4 n), warp tile 64x32.
// Warp inner: 4x4 grid of m16n8k16 MMAs, 3 products each.
// Smem tiles row-major [row][k], stride 40 bf16 (pad 16B -> ldmatrix
// conflict-free: 8 row addrs hit distinct 16B banks).
// ---------------------------------------------------------------------------
#define GBM 128
#define GBN 128
#define GBK 32
#define GSTR 40   // smem row stride in bf16

__global__ __launch_bounds__(256, 1) void gemm_mma_kernel(
    const __nv_bfloat16* __restrict__ Ahi, const __nv_bfloat16* __restrict__ Alo,
    const __nv_bfloat16* __restrict__ Whi, const __nv_bfloat16* __restrict__ Wlo,
    const float* __restrict__ bias, float* __restrict__ C)
{
    extern __shared__ __align__(16) __nv_bfloat16 sm[];
    __nv_bfloat16* sAh = sm;                  // [128][GSTR]
    __nv_bfloat16* sAl = sAh + GBM * GSTR;
    __nv_bfloat16* sWh = sAl + GBM * GSTR;
    __nv_bfloat16* sWl = sWh + GBM * GSTR;

    const int tid  = threadIdx.x;
    const int wid  = tid >> 5;
    const int lane = tid & 31;
    const int m0 = blockIdx.y * GBM;
    const int n0 = blockIdx.x * GBN;
    const int wm = (wid >> 2) * 64;   // warp m offset in CTA tile
    const int wn = (wid & 3) * 32;    // warp n offset

    float acc[4][4][4] = {};          // [mt][nt][c0..c3]

    for (int k0 = 0; k0 < AD; k0 += GBK) {
        __syncthreads();   // previous compute done reading smem
        // load 4 tiles: each 128 rows x 32 bf16 (64B/row = 4 x 16B chunks)
        #pragma unroll
        for (int c = 0; c < 2; c++) {
            const int chunk = tid + c * 256;     // 0..511
            const int r  = chunk >> 2;           // 0..127
            const int kc = (chunk & 3) * 8;      // bf16 offset in row
            const size_t ga = (size_t)(m0 + r) * AD + k0 + kc;
            const size_t gw = (size_t)(n0 + r) * AD + k0 + kc;
            *(float4*)&sAh[r * GSTR + kc] = *(const float4*)&Ahi[ga];
            *(float4*)&sAl[r * GSTR + kc] = *(const float4*)&Alo[ga];
            *(float4*)&sWh[r * GSTR + kc] = *(const float4*)&Whi[gw];
            *(float4*)&sWl[r * GSTR + kc] = *(const float4*)&Wlo[gw];
        }
        __syncthreads();

        #pragma unroll
        for (int ks = 0; ks < 2; ks++) {
            const int ko = ks * 16;

            // A fragments (hi & lo): 4 m-tiles of 16x16 via ldmatrix.x4
            // addr: row = wm + mt*16 + (lane&15), col = ko + 8*(lane>>4)
            uint32_t ah[4][4], al[4][4];
            {
                const int rr = (lane & 15);
                const int cc = ko + 8 * (lane >> 4);
                #pragma unroll
                for (int mt = 0; mt < 4; mt++) {
                    const int row = wm + mt * 16 + rr;
                    ldmatrix_x4(ah[mt], smem_u32(&sAh[row * GSTR + cc]));
                    ldmatrix_x4(al[mt], smem_u32(&sAl[row * GSTR + cc]));
                }
            }

            // B fragments (hi & lo): 4 n-tiles (8 wide); two x4 loads cover
            // nt pairs (0,1) and (2,3).
            // addr: row = wn + np*16 + (lane&7) + 8*(lane>>4),
            //       col = ko + 8*((lane>>3)&1)
            uint32_t bh[4][2], bl[4][2];
            {
                const int rr = (lane & 7) + 8 * (lane >> 4);
                const int cc = ko + 8 * ((lane >> 3) & 1);
                #pragma unroll
                for (int np = 0; np < 2; np++) {
                    const int row = wn + np * 16 + rr;
                    uint32_t t[4];
                    ldmatrix_x4(t, smem_u32(&sWh[row * GSTR + cc]));
                    bh[2 * np][0] = t[0]; bh[2 * np][1] = t[1];
                    bh[2 * np + 1][0] = t[2]; bh[2 * np + 1][1] = t[3];
                    ldmatrix_x4(t, smem_u32(&sWl[row * GSTR + cc]));
                    bl[2 * np][0] = t[0]; bl[2 * np][1] = t[1];
                    bl[2 * np + 1][0] = t[2]; bl[2 * np + 1][1] = t[3];
                }
            }

            #pragma unroll
            for (int mt = 0; mt < 4; mt++)
                #pragma unroll
                for (int nt = 0; nt < 4; nt++) {
                    mma_bf16(acc[mt][nt], ah[mt], bh[nt]);   // hi*hi
                    mma_bf16(acc[mt][nt], ah[mt], bl[nt]);   // hi*lo
                    mma_bf16(acc[mt][nt], al[mt], bh[nt]);   // lo*hi
                }
        }
    }

    // epilogue: c0=(r,c), c1=(r,c+1), c2=(r+8,c), c3=(r+8,c+1)
    // r = wm + mt*16 + lane/4 ; c = wn + nt*8 + (lane%4)*2
    const int er = lane >> 2;
    const int ec = (lane & 3) * 2;
    #pragma unroll
    for (int mt = 0; mt < 4; mt++) {
        const int row = m0 + wm + mt * 16 + er;
        #pragma unroll
        for (int nt = 0; nt < 4; nt++) {
            const int col = n0 + wn + nt * 8 + ec;
            const float bx = bias[col], by = bias[col + 1];
            float2 v0 = make_float2(acc[mt][nt][0] + bx, acc[mt][nt][1] + by);
            float2 v1 = make_float2(acc[mt][nt][2] + bx, acc[mt][nt][3] + by);
            *(float2*)&C[(size_t)row * AD + col]       = v0;
            *(float2*)&C[(size_t)(row + 8) * AD + col] = v1;
        }
    }
}

#define GEMM_SMEM (4 * GBM * GSTR * (int)sizeof(__nv_bfloat16))   // 40960 B

// ---------------------------------------------------------------------------
// Flash attention (causal), fp32, online softmax — unchanged from R1.
// ---------------------------------------------------------------------------
#define LDP 65

__global__ __launch_bounds__(256) void flash_attn_kernel(
    const float* __restrict__ q, const float* __restrict__ k,
    const float* __restrict__ v, float* __restrict__ o)
{
    extern __shared__ float fsmem[];
    float* Qs  = fsmem;
    float* KVs = fsmem + 64 * LDP;
    float* Ps  = fsmem + 2 * 64 * LDP;

    const int tid = threadIdx.x;
    const int tx = tid & 15;
    const int ty = tid >> 4;
    const int qt = blockIdx.x;
    const int b  = blockIdx.y / AH;
    const int h  = blockIdx.y % AH;

    const size_t base = (size_t)b * AS * AD + (size_t)h * AHD;
    const float* qb = q + base;
    const float* kb = k + base;
    const float* vb = v + base;
    float*       ob = o + base;

    const int q0 = qt * 64;

    for (int i = tid; i < 64 * 64; i += 256) {
        const int r = i >> 6, c = i & 63;
        Qs[r * LDP + c] = qb[(size_t)(q0 + r) * AD + c];
    }

    float m_i[4], l_i[4], acc[4][4] = {};
    #pragma unroll
    for (int i = 0; i < 4; i++) { m_i[i] = -1e30f; l_i[i] = 0.0f; }

    const float scale = 0.125f;

    for (int kt = 0; kt <= qt; kt++) {
        const int k0 = kt * 64;

        __syncthreads();

        for (int i = tid; i < 64 * 64; i += 256) {
            const int r = i >> 6, c = i & 63;
            KVs[r * LDP + c] = kb[(size_t)(k0 + r) * AD + c];
        }
        __syncthreads();

        float s[4][4] = {};
        #pragma unroll 8
        for (int kk = 0; kk < 64; kk++) {
            float a[4], bb[4];
            #pragma unroll
            for (int i = 0; i < 4; i++) a[i]  = Qs[(4 * ty + i) * LDP + kk];
            #pragma unroll
            for (int j = 0; j < 4; j++) bb[j] = KVs[(4 * tx + j) * LDP + kk];
            #pragma unroll
            for (int i = 0; i < 4; i++)
                #pragma unroll
                for (int j = 0; j < 4; j++)
                    s[i][j] = fmaf(a[i], bb[j], s[i][j]);
        }
        __syncthreads();

        for (int i = tid; i < 64 * 64; i += 256) {
            const int r = i >> 6, c = i & 63;
            KVs[r * LDP + c] = vb[(size_t)(k0 + r) * AD + c];
        }

        const bool diag = (kt == qt);
        #pragma unroll
        for (int i = 0; i < 4; i++) {
            const int qrow = q0 + 4 * ty + i;
            float sv[4];
            #pragma unroll
            for (int j = 0; j < 4; j++) {
                float val = s[i][j] * scale;
                if (diag && (k0 + 4 * tx + j > qrow)) val = -1e30f;
                sv[j] = val;
            }
            float mx = fmaxf(fmaxf(sv[0], sv[1]), fmaxf(sv[2], sv[3]));
            #pragma unroll
            for (int off = 8; off >= 1; off >>= 1)
                mx = fmaxf(mx, __shfl_xor_sync(0xffffffffu, mx, off));
            const float mnew  = fmaxf(m_i[i], mx);
            const float alpha = __expf(m_i[i] - mnew);
            float rs = 0.0f;
            #pragma unroll
            for (int j = 0; j < 4; j++) {
                const float p = __expf(sv[j] - mnew);
                Ps[(4 * ty + i) * LDP + 4 * tx + j] = p;
                rs += p;
            }
            #pragma unroll
            for (int off = 8; off >= 1; off >>= 1)
                rs += __shfl_xor_sync(0xffffffffu, rs, off);
            l_i[i] = l_i[i] * alpha + rs;
            m_i[i] = mnew;
            #pragma unroll
            for (int j = 0; j < 4; j++) acc[i][j] *= alpha;
        }
        __syncthreads();

        #pragma unroll 4
        for (int kk = 0; kk < 64; kk++) {
            float a[4], vv[4];
            #pragma unroll
            for (int i = 0; i < 4; i++) a[i]  = Ps[(4 * ty + i) * LDP + kk];
            #pragma unroll
            for (int j = 0; j < 4; j++) vv[j] = KVs[kk * LDP + 4 * tx + j];
            #pragma unroll
            for (int i = 0; i < 4; i++)
                #pragma unroll
                for (int j = 0; j < 4; j++)
                    acc[i][j] = fmaf(a[i], vv[j], acc[i][j]);
        }
    }

    #pragma unroll
    for (int i = 0; i < 4; i++) {
        const float inv = 1.0f / l_i[i];
        const size_t row = (size_t)(q0 + 4 * ty + i) * AD;
        #pragma unroll
        for (int j = 0; j < 4; j++)
            ob[row + 4 * tx + j] = acc[i][j] * inv;
    }
}

// ---------------------------------------------------------------------------
// Launch
// ---------------------------------------------------------------------------
extern "C" void kernel_launch(void* const* d_in, const int* in_sizes, int n_in,
                              void* d_out, int out_size)
{
    const float* x  = (const float*)d_in[0];
    const float* wq = (const float*)d_in[1];
    const float* bq = (const float*)d_in[2];
    const float* wk = (const float*)d_in[3];
    const float* bk = (const float*)d_in[4];
    const float* wv = (const float*)d_in[5];
    const float* bv = (const float*)d_in[6];
    const float* wo = (const float*)d_in[7];
    const float* bo = (const float*)d_in[8];
    float* out = (float*)d_out;

    float *gq, *gk, *gv, *ga;
    cudaGetSymbolAddress((void**)&gq, g_q);
    cudaGetSymbolAddress((void**)&gk, g_k);
    cudaGetSymbolAddress((void**)&gv, g_v);
    cudaGetSymbolAddress((void**)&ga, g_attn);

    __nv_bfloat16 *xhi, *xlo, *whi, *wlo, *ahi, *alo;
    cudaGetSymbolAddress((void**)&xhi, g_xhi);
    cudaGetSymbolAddress((void**)&xlo, g_xlo);
    cudaGetSymbolAddress((void**)&whi, g_whi);
    cudaGetSymbolAddress((void**)&wlo, g_wlo);
    cudaGetSymbolAddress((void**)&ahi, g_ahi);
    cudaGetSymbolAddress((void**)&alo, g_alo);

    cudaFuncSetAttribute(gemm_mma_kernel,
                         cudaFuncAttributeMaxDynamicSharedMemorySize, GEMM_SMEM);
    cudaFuncSetAttribute(flash_attn_kernel,
                         cudaFuncAttributeMaxDynamicSharedMemorySize,
                         (int)(3 * 64 * LDP * sizeof(float)));

    // 1) split conversions: x, 4 weights
    {
        const int n4x = AM * AD / 4;        // 1,048,576
        split_kernel<<<(n4x + 255) / 256, 256>>>(x, xhi, xlo, n4x);
        const int n4w = AD * AD / 4;        // 262,144
        const float* ws[4] = {wq, wk, wv, wo};
        for (int i = 0; i < 4; i++)
            split_kernel<<<(n4w + 255) / 256, 256>>>(ws[i], whi + (size_t)i * AD * AD,
                                                     wlo + (size_t)i * AD * AD, n4w);
    }

    dim3 ggrid(AD / GBN, AM / GBM);   // (8, 32)

    // 2) Q/K/V projections on tensor cores (mma.sync)
    gemm_mma_kernel<<<ggrid, 256, GEMM_SMEM>>>(xhi, xlo, whi + 0 * (size_t)AD * AD,
                                               wlo + 0 * (size_t)AD * AD, bq, gq);
    gemm_mma_kernel<<<ggrid, 256, GEMM_SMEM>>>(xhi, xlo, whi + 1 * (size_t)AD * AD,
                                               wlo + 1 * (size_t)AD * AD, bk, gk);
    gemm_mma_kernel<<<ggrid, 256, GEMM_SMEM>>>(xhi, xlo, whi + 2 * (size_t)AD * AD,
                                               wlo + 2 * (size_t)AD * AD, bv, gv);

    // 3) flash attention (fp32)
    const size_t shm = (size_t)3 * 64 * LDP * sizeof(float);
    flash_attn_kernel<<<dim3(AS / 64, AB * AH), 256, shm>>>(gq, gk, gv, ga);

    // 4) split attn output, then output projection
    {
        const int n4a = AM * AD / 4;
        split_kernel<<<(n4a + 255) / 256, 256>>>(ga, ahi, alo, n4a);
    }
    gemm_mma_kernel<<<ggrid, 256, GEMM_SMEM>>>(ahi, alo, whi + 3 * (size_t)AD * AD,
                                               wlo + 3 * (size_t)AD * AD, bo, out);
}

// round 10
// speedup vs baseline: 2.0994x; 1.5879x over previous
#include <cuda_runtime.h>
#include <cuda_bf16.h>
#include <cstdint>
#include <math.h>

// ---------------------------------------------------------------------------
// Problem constants (B=2, S=2048, D=1024, H=16, Hd=64)
// ---------------------------------------------------------------------------
#define AB 2
#define AS 2048
#define AD 1024
#define AH 16
#define AHD 64
#define AM (AB * AS)          // 4096 rows

// fp32 scratch
__device__ __align__(256) float g_q[AM * AD];
__device__ __align__(256) float g_k[AM * AD];
__device__ __align__(256) float g_v[AM * AD];
__device__ __align__(256) float g_attn[AM * AD];

// bf16 hi/lo split scratch for GEMMs
__device__ __align__(256) __nv_bfloat16 g_xhi[AM * AD];
__device__ __align__(256) __nv_bfloat16 g_xlo[AM * AD];
__device__ __align__(256) __nv_bfloat16 g_whi[4][AD * AD];
__device__ __align__(256) __nv_bfloat16 g_wlo[4][AD * AD];
__device__ __align__(256) __nv_bfloat16 g_ahi[AM * AD];
__device__ __align__(256) __nv_bfloat16 g_alo[AM * AD];

// bf16 hi/lo head-major q/k/v for attention: [B*H][S][64]
#define AHS (AB * AH * AS * AHD)
__device__ __align__(256) __nv_bfloat16 g_qhi[AHS];
__device__ __align__(256) __nv_bfloat16 g_qlo[AHS];
__device__ __align__(256) __nv_bfloat16 g_khi[AHS];
__device__ __align__(256) __nv_bfloat16 g_klo[AHS];
__device__ __align__(256) __nv_bfloat16 g_vhi[AHS];
__device__ __align__(256) __nv_bfloat16 g_vlo[AHS];

// ---------------------------------------------------------------------------
// mma.sync helpers
// ---------------------------------------------------------------------------
__device__ __forceinline__ uint32_t smem_u32(const void* p) {
    return (uint32_t)__cvta_generic_to_shared(p);
}

__device__ __forceinline__ void ldmatrix_x4(uint32_t* r, uint32_t addr) {
    asm volatile("ldmatrix.sync.aligned.m8n8.x4.shared.b16 {%0,%1,%2,%3}, [%4];"
        : "=r"(r[0]), "=r"(r[1]), "=r"(r[2]), "=r"(r[3]) : "r"(addr));
}

__device__ __forceinline__ void ldmatrix_x4_trans(uint32_t* r, uint32_t addr) {
    asm volatile("ldmatrix.sync.aligned.m8n8.x4.trans.shared.b16 {%0,%1,%2,%3}, [%4];"
        : "=r"(r[0]), "=r"(r[1]), "=r"(r[2]), "=r"(r[3]) : "r"(addr));
}

__device__ __forceinline__ void mma_bf16(float* c, const uint32_t* a, const uint32_t* b) {
    asm volatile(
        "mma.sync.aligned.m16n8k16.row.col.f32.bf16.bf16.f32 "
        "{%0,%1,%2,%3}, {%4,%5,%6,%7}, {%8,%9}, {%0,%1,%2,%3};"
        : "+f"(c[0]), "+f"(c[1]), "+f"(c[2]), "+f"(c[3])
        : "r"(a[0]), "r"(a[1]), "r"(a[2]), "r"(a[3]), "r"(b[0]), "r"(b[1]));
}

__device__ __forceinline__ uint32_t pack_bf16(float a, float b) {
    __nv_bfloat162 t;
    t.x = __float2bfloat16(a);
    t.y = __float2bfloat16(b);
    return *(uint32_t*)&t;
}

// exp on fma/alu pipes (no MUFU): 2^t with t = x*log2e, i = rint(t),
// deg-4 Taylor of 2^f on [-0.5, 0.5] (max err ~4e-5).
__device__ __forceinline__ float exp_approx(float x) {
    float t = x * 1.44269504f;
    t = fmaxf(t, -126.0f);
    float fi = rintf(t);
    float f = t - fi;
    float p = fmaf(f, 0.00961812f, 0.05550411f);
    p = fmaf(f, p, 0.24022651f);
    p = fmaf(f, p, 0.69314718f);
    p = fmaf(f, p, 1.0f);
    int e = (int)fi;
    return p * __int_as_float((e + 127) << 23);
}

// ---------------------------------------------------------------------------
// fp32 -> bf16 hi/lo split (flat, for GEMM operands)
// ---------------------------------------------------------------------------
__global__ __launch_bounds__(256) void split_kernel(
    const float* __restrict__ src, __nv_bfloat16* __restrict__ hi,
    __nv_bfloat16* __restrict__ lo, int n4)
{
    int i = blockIdx.x * blockDim.x + threadIdx.x;
    if (i >= n4) return;
    float4 v = ((const float4*)src)[i];
    __nv_bfloat16 h0 = __float2bfloat16(v.x);
    __nv_bfloat16 h1 = __float2bfloat16(v.y);
    __nv_bfloat16 h2 = __float2bfloat16(v.z);
    __nv_bfloat16 h3 = __float2bfloat16(v.w);
    __nv_bfloat162 hp0; hp0.x = h0; hp0.y = h1;
    __nv_bfloat162 hp1; hp1.x = h2; hp1.y = h3;
    ((__nv_bfloat162*)hi)[2 * i]     = hp0;
    ((__nv_bfloat162*)hi)[2 * i + 1] = hp1;
    __nv_bfloat162 lp0, lp1;
    lp0.x = __float2bfloat16(v.x - __bfloat162float(h0));
    lp0.y = __float2bfloat16(v.y - __bfloat162float(h1));
    lp1.x = __float2bfloat16(v.z - __bfloat162float(h2));
    lp1.y = __float2bfloat16(v.w - __bfloat162float(h3));
    ((__nv_bfloat162*)lo)[2 * i]     = lp0;
    ((__nv_bfloat162*)lo)[2 * i + 1] = lp1;
}

// ---------------------------------------------------------------------------
// fp32 [B,S,H*64] -> bf16 hi/lo [B*H][S][64], optional scale folded in.
// One thread per 4 elements along d.
// ---------------------------------------------------------------------------
__global__ __launch_bounds__(256) void attn_split_kernel(
    const float* __restrict__ src, __nv_bfloat16* __restrict__ hi,
    __nv_bfloat16* __restrict__ lo, float scale)
{
    int i = blockIdx.x * blockDim.x + threadIdx.x;   // 0 .. B*H*S*16 - 1
    const int d4 = (i & 15) * 4;
    const int s  = (i >> 4) & (AS - 1);
    const int bh = i >> 15;                           // 0..31
    if (bh >= AB * AH) return;
    const int b = bh >> 4, h = bh & 15;
    float4 v = *(const float4*)&src[((size_t)(b * AS + s)) * AD + h * AHD + d4];
    v.x *= scale; v.y *= scale; v.z *= scale; v.w *= scale;
    const size_t o = ((size_t)bh * AS + s) * AHD + d4;
    __nv_bfloat16 h0 = __float2bfloat16(v.x);
    __nv_bfloat16 h1 = __float2bfloat16(v.y);
    __nv_bfloat16 h2 = __float2bfloat16(v.z);
    __nv_bfloat16 h3 = __float2bfloat16(v.w);
    __nv_bfloat162 hp0; hp0.x = h0; hp0.y = h1;
    __nv_bfloat162 hp1; hp1.x = h2; hp1.y = h3;
    *(__nv_bfloat162*)&hi[o]     = hp0;
    *(__nv_bfloat162*)&hi[o + 2] = hp1;
    __nv_bfloat162 lp0, lp1;
    lp0.x = __float2bfloat16(v.x - __bfloat162float(h0));
    lp0.y = __float2bfloat16(v.y - __bfloat162float(h1));
    lp1.x = __float2bfloat16(v.z - __bfloat162float(h2));
    lp1.y = __float2bfloat16(v.w - __bfloat162float(h3));
    *(__nv_bfloat162*)&lo[o]     = lp0;
    *(__nv_bfloat162*)&lo[o + 2] = lp1;
}

// ---------------------------------------------------------------------------
// bf16 split GEMM via mma.sync (validated R6):  C = A @ W^T + bias
// ---------------------------------------------------------------------------
#define GBM 128
#define GBN 128
#define GBK 32
#define GSTR 40

__global__ __launch_bounds__(256, 1) void gemm_mma_kernel(
    const __nv_bfloat16* __restrict__ Ahi, const __nv_bfloat16* __restrict__ Alo,
    const __nv_bfloat16* __restrict__ Whi, const __nv_bfloat16* __restrict__ Wlo,
    const float* __restrict__ bias, float* __restrict__ C)
{
    extern __shared__ __align__(16) __nv_bfloat16 sm[];
    __nv_bfloat16* sAh = sm;
    __nv_bfloat16* sAl = sAh + GBM * GSTR;
    __nv_bfloat16* sWh = sAl + GBM * GSTR;
    __nv_bfloat16* sWl = sWh + GBM * GSTR;

    const int tid  = threadIdx.x;
    const int wid  = tid >> 5;
    const int lane = tid & 31;
    const int m0 = blockIdx.y * GBM;
    const int n0 = blockIdx.x * GBN;
    const int wm = (wid >> 2) * 64;
    const int wn = (wid & 3) * 32;

    float acc[4][4][4] = {};

    for (int k0 = 0; k0 < AD; k0 += GBK) {
        __syncthreads();
        #pragma unroll
        for (int c = 0; c < 2; c++) {
            const int chunk = tid + c * 256;
            const int r  = chunk >> 2;
            const int kc = (chunk & 3) * 8;
            const size_t ga = (size_t)(m0 + r) * AD + k0 + kc;
            const size_t gw = (size_t)(n0 + r) * AD + k0 + kc;
            *(float4*)&sAh[r * GSTR + kc] = *(const float4*)&Ahi[ga];
            *(float4*)&sAl[r * GSTR + kc] = *(const float4*)&Alo[ga];
            *(float4*)&sWh[r * GSTR + kc] = *(const float4*)&Whi[gw];
            *(float4*)&sWl[r * GSTR + kc] = *(const float4*)&Wlo[gw];
        }
        __syncthreads();

        #pragma unroll
        for (int ks = 0; ks < 2; ks++) {
            const int ko = ks * 16;
            uint32_t ah[4][4], al[4][4];
            {
                const int rr = (lane & 15);
                const int cc = ko + 8 * (lane >> 4);
                #pragma unroll
                for (int mt = 0; mt < 4; mt++) {
                    const int row = wm + mt * 16 + rr;
                    ldmatrix_x4(ah[mt], smem_u32(&sAh[row * GSTR + cc]));
                    ldmatrix_x4(al[mt], smem_u32(&sAl[row * GSTR + cc]));
                }
            }
            uint32_t bh[4][2], bl[4][2];
            {
                const int rr = (lane & 7) + 8 * (lane >> 4);
                const int cc = ko + 8 * ((lane >> 3) & 1);
                #pragma unroll
                for (int np = 0; np < 2; np++) {
                    const int row = wn + np * 16 + rr;
                    uint32_t t[4];
                    ldmatrix_x4(t, smem_u32(&sWh[row * GSTR + cc]));
                    bh[2 * np][0] = t[0]; bh[2 * np][1] = t[1];
                    bh[2 * np + 1][0] = t[2]; bh[2 * np + 1][1] = t[3];
                    ldmatrix_x4(t, smem_u32(&sWl[row * GSTR + cc]));
                    bl[2 * np][0] = t[0]; bl[2 * np][1] = t[1];
                    bl[2 * np + 1][0] = t[2]; bl[2 * np + 1][1] = t[3];
                }
            }
            #pragma unroll
            for (int mt = 0; mt < 4; mt++)
                #pragma unroll
                for (int nt = 0; nt < 4; nt++) {
                    mma_bf16(acc[mt][nt], ah[mt], bh[nt]);
                    mma_bf16(acc[mt][nt], ah[mt], bl[nt]);
                    mma_bf16(acc[mt][nt], al[mt], bh[nt]);
                }
        }
    }

    const int er = lane >> 2;
    const int ec = (lane & 3) * 2;
    #pragma unroll
    for (int mt = 0; mt < 4; mt++) {
        const int row = m0 + wm + mt * 16 + er;
        #pragma unroll
        for (int nt = 0; nt < 4; nt++) {
            const int col = n0 + wn + nt * 8 + ec;
            const float bx = bias[col], by = bias[col + 1];
            float2 v0 = make_float2(acc[mt][nt][0] + bx, acc[mt][nt][1] + by);
            float2 v1 = make_float2(acc[mt][nt][2] + bx, acc[mt][nt][3] + by);
            *(float2*)&C[(size_t)row * AD + col]       = v0;
            *(float2*)&C[(size_t)(row + 8) * AD + col] = v1;
        }
    }
}

#define GEMM_SMEM (4 * GBM * GSTR * (int)sizeof(__nv_bfloat16))

// ---------------------------------------------------------------------------
// Tensorized flash attention (causal), hi/lo bf16 split, poly exp.
// CTA: 128 q-rows of one (b,h). 256 threads = 8 warps; warp w owns rows
// q0+16w..+15. kt tiles of 64 keys. Scale (1/8) folded into Q split.
// Smem union: Q stage (2 x 128 x 72) then per-kt K/V hi/lo (4 x 64 x 72).
// ---------------------------------------------------------------------------
#define FP 72   // smem pitch in bf16 (144B = 9 x 16B banks, odd -> conflict-free)
#define FLASH_SMEM (4 * 64 * FP * (int)sizeof(__nv_bfloat16))   // 36864 B

__global__ __launch_bounds__(256) void flash_mma_kernel(
    const __nv_bfloat16* __restrict__ qhi, const __nv_bfloat16* __restrict__ qlo,
    const __nv_bfloat16* __restrict__ khi, const __nv_bfloat16* __restrict__ klo,
    const __nv_bfloat16* __restrict__ vhi, const __nv_bfloat16* __restrict__ vlo,
    float* __restrict__ o)
{
    extern __shared__ __align__(16) __nv_bfloat16 fsm[];
    __nv_bfloat16* sQh = fsm;                 // stage phase: [128][FP]
    __nv_bfloat16* sQl = fsm + 128 * FP;
    __nv_bfloat16* sKh = fsm;                 // loop phase: [64][FP] x4
    __nv_bfloat16* sKl = fsm + 64 * FP;
    __nv_bfloat16* sVh = fsm + 2 * 64 * FP;
    __nv_bfloat16* sVl = fsm + 3 * 64 * FP;

    const int tid  = threadIdx.x;
    const int wid  = tid >> 5;
    const int lane = tid & 31;
    const int qt = blockIdx.x;
    const int bh = blockIdx.y;
    const int q0 = qt * 128;

    const size_t hb = (size_t)bh * AS * AHD;
    const __nv_bfloat16* Qh = qhi + hb;
    const __nv_bfloat16* Ql = qlo + hb;
    const __nv_bfloat16* Kh = khi + hb;
    const __nv_bfloat16* Kl = klo + hb;
    const __nv_bfloat16* Vh = vhi + hb;
    const __nv_bfloat16* Vl = vlo + hb;

    // ---- stage Q tile, extract per-warp A fragments (kept in regs) ----
    for (int i = tid; i < 128 * 8; i += 256) {
        const int r = i >> 3, c8 = (i & 7) * 8;
        *(float4*)&sQh[r * FP + c8] = *(const float4*)&Qh[(size_t)(q0 + r) * AHD + c8];
        *(float4*)&sQl[r * FP + c8] = *(const float4*)&Ql[(size_t)(q0 + r) * AHD + c8];
    }
    __syncthreads();

    uint32_t qfh[4][4], qfl[4][4];
    {
        const int rr = wid * 16 + (lane & 15);
        const int cc = 8 * (lane >> 4);
        #pragma unroll
        for (int ks = 0; ks < 4; ks++) {
            ldmatrix_x4(qfh[ks], smem_u32(&sQh[rr * FP + ks * 16 + cc]));
            ldmatrix_x4(qfl[ks], smem_u32(&sQl[rr * FP + ks * 16 + cc]));
        }
    }

    float oacc[8][4] = {};
    float m0 = -1e30f, m1 = -1e30f, l0 = 0.0f, l1 = 0.0f;
    const int wqlo = q0 + wid * 16;
    const int wqhi = wqlo + 15;

    const int ktmax = 2 * qt + 1;
    for (int kt = 0; kt <= ktmax; kt++) {
        const int k0 = kt * 64;
        __syncthreads();   // Q frags extracted (kt=0) / prev compute done

        for (int i = tid; i < 64 * 8; i += 256) {
            const int r = i >> 3, c8 = (i & 7) * 8;
            const size_t g = (size_t)(k0 + r) * AHD + c8;
            *(float4*)&sKh[r * FP + c8] = *(const float4*)&Kh[g];
            *(float4*)&sKl[r * FP + c8] = *(const float4*)&Kl[g];
            *(float4*)&sVh[r * FP + c8] = *(const float4*)&Vh[g];
            *(float4*)&sVl[r * FP + c8] = *(const float4*)&Vl[g];
        }
        __syncthreads();

        if (k0 > wqhi) continue;   // tile fully masked for this warp

        // ---- S = Q K^T (3-way split) ----
        float sacc[8][4] = {};
        {
            const int rrB = (lane & 7) + 8 * (lane >> 4);
            const int ccB0 = 8 * ((lane >> 3) & 1);
            #pragma unroll
            for (int ks = 0; ks < 4; ks++) {
                const int cc = ks * 16 + ccB0;
                #pragma unroll
                for (int np = 0; np < 4; np++) {
                    uint32_t th[4], tl[4];
                    ldmatrix_x4(th, smem_u32(&sKh[(np * 16 + rrB) * FP + cc]));
                    ldmatrix_x4(tl, smem_u32(&sKl[(np * 16 + rrB) * FP + cc]));
                    mma_bf16(sacc[2 * np],     qfh[ks], &th[0]);
                    mma_bf16(sacc[2 * np + 1], qfh[ks], &th[2]);
                    mma_bf16(sacc[2 * np],     qfh[ks], &tl[0]);
                    mma_bf16(sacc[2 * np + 1], qfh[ks], &tl[2]);
                    mma_bf16(sacc[2 * np],     qfl[ks], &th[0]);
                    mma_bf16(sacc[2 * np + 1], qfl[ks], &th[2]);
                }
            }
        }

        // ---- causal mask (diagonal tiles only) ----
        const int row0 = wqlo + (lane >> 2);
        const int row1 = row0 + 8;
        if (k0 + 63 > wqlo) {
            #pragma unroll
            for (int nt = 0; nt < 8; nt++) {
                const int col = k0 + nt * 8 + (lane & 3) * 2;
                if (col     > row0) sacc[nt][0] = -1e30f;
                if (col + 1 > row0) sacc[nt][1] = -1e30f;
                if (col     > row1) sacc[nt][2] = -1e30f;
                if (col + 1 > row1) sacc[nt][3] = -1e30f;
            }
        }

        // ---- online softmax (FMA-pipe exp) ----
        float mx0 = -1e30f, mx1 = -1e30f;
        #pragma unroll
        for (int nt = 0; nt < 8; nt++) {
            mx0 = fmaxf(mx0, fmaxf(sacc[nt][0], sacc[nt][1]));
            mx1 = fmaxf(mx1, fmaxf(sacc[nt][2], sacc[nt][3]));
        }
        mx0 = fmaxf(mx0, __shfl_xor_sync(0xffffffffu, mx0, 1));
        mx0 = fmaxf(mx0, __shfl_xor_sync(0xffffffffu, mx0, 2));
        mx1 = fmaxf(mx1, __shfl_xor_sync(0xffffffffu, mx1, 1));
        mx1 = fmaxf(mx1, __shfl_xor_sync(0xffffffffu, mx1, 2));

        const float mn0 = fmaxf(m0, mx0), mn1 = fmaxf(m1, mx1);
        const float a0 = exp_approx(m0 - mn0), a1 = exp_approx(m1 - mn1);
        m0 = mn0; m1 = mn1;

        float rs0 = 0.0f, rs1 = 0.0f;
        #pragma unroll
        for (int nt = 0; nt < 8; nt++) {
            float p0 = exp_approx(sacc[nt][0] - mn0);
            float p1 = exp_approx(sacc[nt][1] - mn0);
            float p2 = exp_approx(sacc[nt][2] - mn1);
            float p3 = exp_approx(sacc[nt][3] - mn1);
            sacc[nt][0] = p0; sacc[nt][1] = p1; sacc[nt][2] = p2; sacc[nt][3] = p3;
            rs0 += p0 + p1; rs1 += p2 + p3;
        }
        rs0 += __shfl_xor_sync(0xffffffffu, rs0, 1);
        rs0 += __shfl_xor_sync(0xffffffffu, rs0, 2);
        rs1 += __shfl_xor_sync(0xffffffffu, rs1, 1);
        rs1 += __shfl_xor_sync(0xffffffffu, rs1, 2);
        l0 = l0 * a0 + rs0;
        l1 = l1 * a1 + rs1;

        #pragma unroll
        for (int nt = 0; nt < 8; nt++) {
            oacc[nt][0] *= a0; oacc[nt][1] *= a0;
            oacc[nt][2] *= a1; oacc[nt][3] *= a1;
        }

        // ---- O += P V (3-way split); P frags built from sacc in-regs ----
        {
            const int rrV0 = (lane & 15);
            const int ccV0 = 8 * (lane >> 4);
            #pragma unroll
            for (int ks = 0; ks < 4; ks++) {
                uint32_t pa[4], pl[4];
                {
                    const float c0 = sacc[2 * ks][0],     c1 = sacc[2 * ks][1];
                    const float c2 = sacc[2 * ks][2],     c3 = sacc[2 * ks][3];
                    const float d0 = sacc[2 * ks + 1][0], d1 = sacc[2 * ks + 1][1];
                    const float d2 = sacc[2 * ks + 1][2], d3 = sacc[2 * ks + 1][3];
                    pa[0] = pack_bf16(c0, c1);
                    pa[1] = pack_bf16(c2, c3);
                    pa[2] = pack_bf16(d0, d1);
                    pa[3] = pack_bf16(d2, d3);
                    __nv_bfloat162 h;
                    h = *(__nv_bfloat162*)&pa[0];
                    pl[0] = pack_bf16(c0 - __bfloat162float(h.x), c1 - __bfloat162float(h.y));
                    h = *(__nv_bfloat162*)&pa[1];
                    pl[1] = pack_bf16(c2 - __bfloat162float(h.x), c3 - __bfloat162float(h.y));
                    h = *(__nv_bfloat162*)&pa[2];
                    pl[2] = pack_bf16(d0 - __bfloat162float(h.x), d1 - __bfloat162float(h.y));
                    h = *(__nv_bfloat162*)&pa[3];
                    pl[3] = pack_bf16(d2 - __bfloat162float(h.x), d3 - __bfloat162float(h.y));
                }
                const int rrV = ks * 16 + rrV0;
                #pragma unroll
                for (int np = 0; np < 4; np++) {
                    uint32_t th[4], tl[4];
                    ldmatrix_x4_trans(th, smem_u32(&sVh[rrV * FP + np * 16 + ccV0]));
                    ldmatrix_x4_trans(tl, smem_u32(&sVl[rrV * FP + np * 16 + ccV0]));
                    mma_bf16(oacc[2 * np],     pa, &th[0]);
                    mma_bf16(oacc[2 * np + 1], pa, &th[2]);
                    mma_bf16(oacc[2 * np],     pa, &tl[0]);
                    mma_bf16(oacc[2 * np + 1], pa, &tl[2]);
                    mma_bf16(oacc[2 * np],     pl, &th[0]);
                    mma_bf16(oacc[2 * np + 1], pl, &th[2]);
                }
            }
        }
    }

    // ---- epilogue: normalize, write to g_attn [B,S,H*64] fp32 ----
    const float inv0 = 1.0f / l0;
    const float inv1 = 1.0f / l1;
    const int b = bh >> 4, h = bh & 15;
    const int row0g = q0 + wid * 16 + (lane >> 2);
    const size_t obase = (size_t)b * AS * AD + (size_t)h * AHD;
    #pragma unroll
    for (int nt = 0; nt < 8; nt++) {
        const int col = nt * 8 + (lane & 3) * 2;
        float2 v0 = make_float2(oacc[nt][0] * inv0, oacc[nt][1] * inv0);
        float2 v1 = make_float2(oacc[nt][2] * inv1, oacc[nt][3] * inv1);
        *(float2*)&o[obase + (size_t)row0g * AD + col]       = v0;
        *(float2*)&o[obase + (size_t)(row0g + 8) * AD + col] = v1;
    }
}

// ---------------------------------------------------------------------------
// Launch
// ---------------------------------------------------------------------------
extern "C" void kernel_launch(void* const* d_in, const int* in_sizes, int n_in,
                              void* d_out, int out_size)
{
    const float* x  = (const float*)d_in[0];
    const float* wq = (const float*)d_in[1];
    const float* bq = (const float*)d_in[2];
    const float* wk = (const float*)d_in[3];
    const float* bk = (const float*)d_in[4];
    const float* wv = (const float*)d_in[5];
    const float* bv = (const float*)d_in[6];
    const float* wo = (const float*)d_in[7];
    const float* bo = (const float*)d_in[8];
    float* out = (float*)d_out;

    float *gq, *gk, *gv, *ga;
    cudaGetSymbolAddress((void**)&gq, g_q);
    cudaGetSymbolAddress((void**)&gk, g_k);
    cudaGetSymbolAddress((void**)&gv, g_v);
    cudaGetSymbolAddress((void**)&ga, g_attn);

    __nv_bfloat16 *xhi, *xlo, *whi, *wlo, *ahi, *alo;
    cudaGetSymbolAddress((void**)&xhi, g_xhi);
    cudaGetSymbolAddress((void**)&xlo, g_xlo);
    cudaGetSymbolAddress((void**)&whi, g_whi);
    cudaGetSymbolAddress((void**)&wlo, g_wlo);
    cudaGetSymbolAddress((void**)&ahi, g_ahi);
    cudaGetSymbolAddress((void**)&alo, g_alo);

    __nv_bfloat16 *qhi, *qlo, *khi, *klo, *vhi, *vlo;
    cudaGetSymbolAddress((void**)&qhi, g_qhi);
    cudaGetSymbolAddress((void**)&qlo, g_qlo);
    cudaGetSymbolAddress((void**)&khi, g_khi);
    cudaGetSymbolAddress((void**)&klo, g_klo);
    cudaGetSymbolAddress((void**)&vhi, g_vhi);
    cudaGetSymbolAddress((void**)&vlo, g_vlo);

    cudaFuncSetAttribute(gemm_mma_kernel,
                         cudaFuncAttributeMaxDynamicSharedMemorySize, GEMM_SMEM);
    cudaFuncSetAttribute(flash_mma_kernel,
                         cudaFuncAttributeMaxDynamicSharedMemorySize, FLASH_SMEM);

    // 1) split x + weights for projection GEMMs
    {
        const int n4x = AM * AD / 4;
        split_kernel<<<(n4x + 255) / 256, 256>>>(x, xhi, xlo, n4x);
        const int n4w = AD * AD / 4;
        const float* ws[4] = {wq, wk, wv, wo};
        for (int i = 0; i < 4; i++)
            split_kernel<<<(n4w + 255) / 256, 256>>>(ws[i], whi + (size_t)i * AD * AD,
                                                     wlo + (size_t)i * AD * AD, n4w);
    }

    dim3 ggrid(AD / GBN, AM / GBM);

    // 2) Q/K/V projections
    gemm_mma_kernel<<<ggrid, 256, GEMM_SMEM>>>(xhi, xlo, whi + 0 * (size_t)AD * AD,
                                               wlo + 0 * (size_t)AD * AD, bq, gq);
    gemm_mma_kernel<<<ggrid, 256, GEMM_SMEM>>>(xhi, xlo, whi + 1 * (size_t)AD * AD,
                                               wlo + 1 * (size_t)AD * AD, bk, gk);
    gemm_mma_kernel<<<ggrid, 256, GEMM_SMEM>>>(xhi, xlo, whi + 2 * (size_t)AD * AD,
                                               wlo + 2 * (size_t)AD * AD, bv, gv);

    // 3) re-layout q/k/v to head-major bf16 hi/lo (scale 1/8 folded into q)
    {
        const int nt = AB * AH * AS * 16;   // threads (4 elems each)
        const int nb = (nt + 255) / 256;
        attn_split_kernel<<<nb, 256>>>(gq, qhi, qlo, 0.125f);
        attn_split_kernel<<<nb, 256>>>(gk, khi, klo, 1.0f);
        attn_split_kernel<<<nb, 256>>>(gv, vhi, vlo, 1.0f);
    }

    // 4) tensorized flash attention
    flash_mma_kernel<<<dim3(AS / 128, AB * AH), 256, FLASH_SMEM>>>(
        qhi, qlo, khi, klo, vhi, vlo, ga);

    // 5) split attn output, then output projection
    {
        const int n4a = AM * AD / 4;
        split_kernel<<<(n4a + 255) / 256, 256>>>(ga, ahi, alo, n4a);
    }
    gemm_mma_kernel<<<ggrid, 256, GEMM_SMEM>>>(ahi, alo, whi + 3 * (size_t)AD * AD,
                                               wlo + 3 * (size_t)AD * AD, bo, out);
}

// round 15
// speedup vs baseline: 2.3622x; 1.1252x over previous
#include <cuda_runtime.h>
#include <cuda_bf16.h>
#include <cstdint>
#include <math.h>

// ---------------------------------------------------------------------------
// Problem constants (B=2, S=2048, D=1024, H=16, Hd=64)
// ---------------------------------------------------------------------------
#define AB 2
#define AS 2048
#define AD 1024
#define AH 16
#define AHD 64
#define AM (AB * AS)          // 4096 rows

// bf16 hi/lo split scratch for GEMM inputs
__device__ __align__(256) __nv_bfloat16 g_xhi[AM * AD];
__device__ __align__(256) __nv_bfloat16 g_xlo[AM * AD];
__device__ __align__(256) __nv_bfloat16 g_whi[4][AD * AD];
__device__ __align__(256) __nv_bfloat16 g_wlo[4][AD * AD];
__device__ __align__(256) __nv_bfloat16 g_ahi[AM * AD];
__device__ __align__(256) __nv_bfloat16 g_alo[AM * AD];

// bf16 hi/lo head-major q/k/v for attention: [B*H][S][64]
#define AHS (AB * AH * AS * AHD)
__device__ __align__(256) __nv_bfloat16 g_qhi[AHS];
__device__ __align__(256) __nv_bfloat16 g_qlo[AHS];
__device__ __align__(256) __nv_bfloat16 g_khi[AHS];
__device__ __align__(256) __nv_bfloat16 g_klo[AHS];
__device__ __align__(256) __nv_bfloat16 g_vhi[AHS];
__device__ __align__(256) __nv_bfloat16 g_vlo[AHS];

// ---------------------------------------------------------------------------
// PTX helpers
// ---------------------------------------------------------------------------
__device__ __forceinline__ uint32_t smem_u32(const void* p) {
    return (uint32_t)__cvta_generic_to_shared(p);
}

__device__ __forceinline__ void ldmatrix_x4(uint32_t* r, uint32_t addr) {
    asm volatile("ldmatrix.sync.aligned.m8n8.x4.shared.b16 {%0,%1,%2,%3}, [%4];"
        : "=r"(r[0]), "=r"(r[1]), "=r"(r[2]), "=r"(r[3]) : "r"(addr));
}

__device__ __forceinline__ void ldmatrix_x4_trans(uint32_t* r, uint32_t addr) {
    asm volatile("ldmatrix.sync.aligned.m8n8.x4.trans.shared.b16 {%0,%1,%2,%3}, [%4];"
        : "=r"(r[0]), "=r"(r[1]), "=r"(r[2]), "=r"(r[3]) : "r"(addr));
}

__device__ __forceinline__ void mma_bf16(float* c, const uint32_t* a, const uint32_t* b) {
    asm volatile(
        "mma.sync.aligned.m16n8k16.row.col.f32.bf16.bf16.f32 "
        "{%0,%1,%2,%3}, {%4,%5,%6,%7}, {%8,%9}, {%0,%1,%2,%3};"
        : "+f"(c[0]), "+f"(c[1]), "+f"(c[2]), "+f"(c[3])
        : "r"(a[0]), "r"(a[1]), "r"(a[2]), "r"(a[3]), "r"(b[0]), "r"(b[1]));
}

__device__ __forceinline__ void cp_async16(uint32_t smem, const void* g) {
    asm volatile("cp.async.cg.shared.global [%0], [%1], 16;" :: "r"(smem), "l"(g));
}
#define CP_COMMIT() asm volatile("cp.async.commit_group;" ::: "memory")
#define CP_WAIT1()  asm volatile("cp.async.wait_group 1;" ::: "memory")
#define CP_WAIT0()  asm volatile("cp.async.wait_group 0;" ::: "memory")

__device__ __forceinline__ uint32_t pack_bf16(float a, float b) {
    __nv_bfloat162 t;
    t.x = __float2bfloat16(a);
    t.y = __float2bfloat16(b);
    return *(uint32_t*)&t;
}

// exp on fma/alu pipes (no MUFU): deg-4 Taylor of 2^f on [-0.5,0.5].
__device__ __forceinline__ float exp_approx(float x) {
    float t = x * 1.44269504f;
    t = fmaxf(t, -126.0f);
    float fi = rintf(t);
    float f = t - fi;
    float p = fmaf(f, 0.00961812f, 0.05550411f);
    p = fmaf(f, p, 0.24022651f);
    p = fmaf(f, p, 0.69314718f);
    p = fmaf(f, p, 1.0f);
    int e = (int)fi;
    return p * __int_as_float((e + 127) << 23);
}

// ---------------------------------------------------------------------------
// fp32 -> bf16 hi/lo split (flat; x + weights only now)
// ---------------------------------------------------------------------------
__global__ __launch_bounds__(256) void split_kernel(
    const float* __restrict__ src, __nv_bfloat16* __restrict__ hi,
    __nv_bfloat16* __restrict__ lo, int n4)
{
    int i = blockIdx.x * blockDim.x + threadIdx.x;
    if (i >= n4) return;
    float4 v = ((const float4*)src)[i];
    __nv_bfloat16 h0 = __float2bfloat16(v.x);
    __nv_bfloat16 h1 = __float2bfloat16(v.y);
    __nv_bfloat16 h2 = __float2bfloat16(v.z);
    __nv_bfloat16 h3 = __float2bfloat16(v.w);
    __nv_bfloat162 hp0; hp0.x = h0; hp0.y = h1;
    __nv_bfloat162 hp1; hp1.x = h2; hp1.y = h3;
    ((__nv_bfloat162*)hi)[2 * i]     = hp0;
    ((__nv_bfloat162*)hi)[2 * i + 1] = hp1;
    __nv_bfloat162 lp0, lp1;
    lp0.x = __float2bfloat16(v.x - __bfloat162float(h0));
    lp0.y = __float2bfloat16(v.y - __bfloat162float(h1));
    lp1.x = __float2bfloat16(v.z - __bfloat162float(h2));
    lp1.y = __float2bfloat16(v.w - __bfloat162float(h3));
    ((__nv_bfloat162*)lo)[2 * i]     = lp0;
    ((__nv_bfloat162*)lo)[2 * i + 1] = lp1;
}

// ---------------------------------------------------------------------------
// bf16 split GEMM via mma.sync, cp.async double-buffered.
//   acc = Ahi*Whi + Ahi*Wlo + Alo*Whi  (fp32)
// outmode 0: C = acc + bias (fp32, row-major [M,1024])
// outmode 1: head-major bf16 hi/lo split of (acc + bias) * scale
// ---------------------------------------------------------------------------
#define GBM 128
#define GBN 128
#define GBK 32
#define GSTR 40
#define GTSZ (GBM * GSTR)              // elems per tile (5120)
#define GEMM_SMEM (2 * 4 * GTSZ * (int)sizeof(__nv_bfloat16))   // 81920 B
#define GNK (AD / GBK)                 // 32 k-chunks

__global__ __launch_bounds__(256, 1) void gemm_mma_kernel(
    const __nv_bfloat16* __restrict__ Ahi, const __nv_bfloat16* __restrict__ Alo,
    const __nv_bfloat16* __restrict__ Whi, const __nv_bfloat16* __restrict__ Wlo,
    const float* __restrict__ bias,
    float* __restrict__ Cf,
    __nv_bfloat16* __restrict__ Chi, __nv_bfloat16* __restrict__ Clo,
    int outmode, float scale)
{
    extern __shared__ __align__(16) __nv_bfloat16 sm[];

    const int tid  = threadIdx.x;
    const int wid  = tid >> 5;
    const int lane = tid & 31;
    const int m0 = blockIdx.y * GBM;
    const int n0 = blockIdx.x * GBN;
    const int wm = (wid >> 2) * 64;
    const int wn = (wid & 3) * 32;

    float acc[4][4][4] = {};

    // prefetch one k-chunk (4 tiles) into stage sb via cp.async, 1 group
    #define GEMM_PREFETCH(K0, SB)                                              \
    {                                                                          \
        __nv_bfloat16* _s = sm + (SB) * 4 * GTSZ;                              \
        _Pragma("unroll")                                                      \
        for (int c = 0; c < 2; c++) {                                          \
            const int chunk = tid + c * 256;                                   \
            const int r  = chunk >> 2;                                         \
            const int kc = (chunk & 3) * 8;                                    \
            const size_t ga = (size_t)(m0 + r) * AD + (K0) + kc;               \
            const size_t gw = (size_t)(n0 + r) * AD + (K0) + kc;               \
            const uint32_t so = smem_u32(&_s[r * GSTR + kc]);                  \
            cp_async16(so + 0 * GTSZ * 2, &Ahi[ga]);                           \
            cp_async16(so + 1 * GTSZ * 2, &Alo[ga]);                           \
            cp_async16(so + 2 * GTSZ * 2, &Whi[gw]);                           \
            cp_async16(so + 3 * GTSZ * 2, &Wlo[gw]);                           \
        }                                                                      \
        CP_COMMIT();                                                           \
    }

    GEMM_PREFETCH(0, 0);

    for (int i = 0; i < GNK; i++) {
        if (i + 1 < GNK) {
            GEMM_PREFETCH((i + 1) * GBK, (i + 1) & 1);
            CP_WAIT1();
        } else {
            CP_WAIT0();
        }
        __syncthreads();

        __nv_bfloat16* sAh = sm + (i & 1) * 4 * GTSZ;
        __nv_bfloat16* sAl = sAh + GTSZ;
        __nv_bfloat16* sWh = sAl + GTSZ;
        __nv_bfloat16* sWl = sWh + GTSZ;

        #pragma unroll
        for (int ks = 0; ks < 2; ks++) {
            const int ko = ks * 16;
            uint32_t ah[4][4], al[4][4];
            {
                const int rr = (lane & 15);
                const int cc = ko + 8 * (lane >> 4);
                #pragma unroll
                for (int mt = 0; mt < 4; mt++) {
                    const int row = wm + mt * 16 + rr;
                    ldmatrix_x4(ah[mt], smem_u32(&sAh[row * GSTR + cc]));
                    ldmatrix_x4(al[mt], smem_u32(&sAl[row * GSTR + cc]));
                }
            }
            uint32_t bh[4][2], bl[4][2];
            {
                const int rr = (lane & 7) + 8 * (lane >> 4);
                const int cc = ko + 8 * ((lane >> 3) & 1);
                #pragma unroll
                for (int np = 0; np < 2; np++) {
                    const int row = wn + np * 16 + rr;
                    uint32_t t[4];
                    ldmatrix_x4(t, smem_u32(&sWh[row * GSTR + cc]));
                    bh[2 * np][0] = t[0]; bh[2 * np][1] = t[1];
                    bh[2 * np + 1][0] = t[2]; bh[2 * np + 1][1] = t[3];
                    ldmatrix_x4(t, smem_u32(&sWl[row * GSTR + cc]));
                    bl[2 * np][0] = t[0]; bl[2 * np][1] = t[1];
                    bl[2 * np + 1][0] = t[2]; bl[2 * np + 1][1] = t[3];
                }
            }
            #pragma unroll
            for (int mt = 0; mt < 4; mt++)
                #pragma unroll
                for (int nt = 0; nt < 4; nt++) {
                    mma_bf16(acc[mt][nt], ah[mt], bh[nt]);
                    mma_bf16(acc[mt][nt], ah[mt], bl[nt]);
                    mma_bf16(acc[mt][nt], al[mt], bh[nt]);
                }
        }
        __syncthreads();   // stage (i&1) free for prefetch i+2
    }
    #undef GEMM_PREFETCH

    const int er = lane >> 2;
    const int ec = (lane & 3) * 2;

    if (outmode == 0) {
        #pragma unroll
        for (int mt = 0; mt < 4; mt++) {
            const int row = m0 + wm + mt * 16 + er;
            #pragma unroll
            for (int nt = 0; nt < 4; nt++) {
                const int col = n0 + wn + nt * 8 + ec;
                const float bx = bias[col], by = bias[col + 1];
                float2 v0 = make_float2(acc[mt][nt][0] + bx, acc[mt][nt][1] + by);
                float2 v1 = make_float2(acc[mt][nt][2] + bx, acc[mt][nt][3] + by);
                *(float2*)&Cf[(size_t)row * AD + col]       = v0;
                *(float2*)&Cf[(size_t)(row + 8) * AD + col] = v1;
            }
        }
    } else {
        // head-major bf16 hi/lo: dest((row,col)) =
        //   (((row>>11)*AH + (col>>6)) * AS + (row & (AS-1))) * AHD + (col & 63)
        #pragma unroll
        for (int mt = 0; mt < 4; mt++) {
            const int row = m0 + wm + mt * 16 + er;
            #pragma unroll
            for (int nt = 0; nt < 4; nt++) {
                const int col = n0 + wn + nt * 8 + ec;
                const float bx = bias[col], by = bias[col + 1];
                const float x0 = (acc[mt][nt][0] + bx) * scale;
                const float x1 = (acc[mt][nt][1] + by) * scale;
                const float x2 = (acc[mt][nt][2] + bx) * scale;
                const float x3 = (acc[mt][nt][3] + by) * scale;
                const int hcol = col >> 6, dcol = col & 63;
                const size_t o0 = (((size_t)((row >> 11) * AH + hcol)) * AS
                                   + (row & (AS - 1))) * AHD + dcol;
                const size_t o1 = (((size_t)(((row + 8) >> 11) * AH + hcol)) * AS
                                   + ((row + 8) & (AS - 1))) * AHD + dcol;
                __nv_bfloat162 h0, h1, l0, l1;
                h0.x = __float2bfloat16(x0); h0.y = __float2bfloat16(x1);
                h1.x = __float2bfloat16(x2); h1.y = __float2bfloat16(x3);
                l0.x = __float2bfloat16(x0 - __bfloat162float(h0.x));
                l0.y = __float2bfloat16(x1 - __bfloat162float(h0.y));
                l1.x = __float2bfloat16(x2 - __bfloat162float(h1.x));
                l1.y = __float2bfloat16(x3 - __bfloat162float(h1.y));
                *(__nv_bfloat162*)&Chi[o0] = h0;
                *(__nv_bfloat162*)&Clo[o0] = l0;
                *(__nv_bfloat162*)&Chi[o1] = h1;
                *(__nv_bfloat162*)&Clo[o1] = l1;
            }
        }
    }
}

// ---------------------------------------------------------------------------
// Tensorized flash attention (validated R10); epilogue writes bf16 hi/lo
// split directly into [M,1024]-layout ahi/alo for the O projection.
// ---------------------------------------------------------------------------
#define FP 72
#define FLASH_SMEM (4 * 64 * FP * (int)sizeof(__nv_bfloat16))   // 36864 B

__global__ __launch_bounds__(256) void flash_mma_kernel(
    const __nv_bfloat16* __restrict__ qhi, const __nv_bfloat16* __restrict__ qlo,
    const __nv_bfloat16* __restrict__ khi, const __nv_bfloat16* __restrict__ klo,
    const __nv_bfloat16* __restrict__ vhi, const __nv_bfloat16* __restrict__ vlo,
    __nv_bfloat16* __restrict__ ahi, __nv_bfloat16* __restrict__ alo)
{
    extern __shared__ __align__(16) __nv_bfloat16 fsm[];
    __nv_bfloat16* sQh = fsm;
    __nv_bfloat16* sQl = fsm + 128 * FP;
    __nv_bfloat16* sKh = fsm;
    __nv_bfloat16* sKl = fsm + 64 * FP;
    __nv_bfloat16* sVh = fsm + 2 * 64 * FP;
    __nv_bfloat16* sVl = fsm + 3 * 64 * FP;

    const int tid  = threadIdx.x;
    const int wid  = tid >> 5;
    const int lane = tid & 31;
    const int qt = blockIdx.x;
    const int bh = blockIdx.y;
    const int q0 = qt * 128;

    const size_t hb = (size_t)bh * AS * AHD;
    const __nv_bfloat16* Qh = qhi + hb;
    const __nv_bfloat16* Ql = qlo + hb;
    const __nv_bfloat16* Kh = khi + hb;
    const __nv_bfloat16* Kl = klo + hb;
    const __nv_bfloat16* Vh = vhi + hb;
    const __nv_bfloat16* Vl = vlo + hb;

    for (int i = tid; i < 128 * 8; i += 256) {
        const int r = i >> 3, c8 = (i & 7) * 8;
        *(float4*)&sQh[r * FP + c8] = *(const float4*)&Qh[(size_t)(q0 + r) * AHD + c8];
        *(float4*)&sQl[r * FP + c8] = *(const float4*)&Ql[(size_t)(q0 + r) * AHD + c8];
    }
    __syncthreads();

    uint32_t qfh[4][4], qfl[4][4];
    {
        const int rr = wid * 16 + (lane & 15);
        const int cc = 8 * (lane >> 4);
        #pragma unroll
        for (int ks = 0; ks < 4; ks++) {
            ldmatrix_x4(qfh[ks], smem_u32(&sQh[rr * FP + ks * 16 + cc]));
            ldmatrix_x4(qfl[ks], smem_u32(&sQl[rr * FP + ks * 16 + cc]));
        }
    }

    float oacc[8][4] = {};
    float m0 = -1e30f, m1 = -1e30f, ln0 = 0.0f, ln1 = 0.0f;
    const int wqlo = q0 + wid * 16;
    const int wqhi = wqlo + 15;

    const int ktmax = 2 * qt + 1;
    for (int kt = 0; kt <= ktmax; kt++) {
        const int k0 = kt * 64;
        __syncthreads();

        for (int i = tid; i < 64 * 8; i += 256) {
            const int r = i >> 3, c8 = (i & 7) * 8;
            const size_t g = (size_t)(k0 + r) * AHD + c8;
            *(float4*)&sKh[r * FP + c8] = *(const float4*)&Kh[g];
            *(float4*)&sKl[r * FP + c8] = *(const float4*)&Kl[g];
            *(float4*)&sVh[r * FP + c8] = *(const float4*)&Vh[g];
            *(float4*)&sVl[r * FP + c8] = *(const float4*)&Vl[g];
        }
        __syncthreads();

        if (k0 > wqhi) continue;

        float sacc[8][4] = {};
        {
            const int rrB = (lane & 7) + 8 * (lane >> 4);
            const int ccB0 = 8 * ((lane >> 3) & 1);
            #pragma unroll
            for (int ks = 0; ks < 4; ks++) {
                const int cc = ks * 16 + ccB0;
                #pragma unroll
                for (int np = 0; np < 4; np++) {
                    uint32_t th[4], tl[4];
                    ldmatrix_x4(th, smem_u32(&sKh[(np * 16 + rrB) * FP + cc]));
                    ldmatrix_x4(tl, smem_u32(&sKl[(np * 16 + rrB) * FP + cc]));
                    mma_bf16(sacc[2 * np],     qfh[ks], &th[0]);
                    mma_bf16(sacc[2 * np + 1], qfh[ks], &th[2]);
                    mma_bf16(sacc[2 * np],     qfh[ks], &tl[0]);
                    mma_bf16(sacc[2 * np + 1], qfh[ks], &tl[2]);
                    mma_bf16(sacc[2 * np],     qfl[ks], &th[0]);
                    mma_bf16(sacc[2 * np + 1], qfl[ks], &th[2]);
                }
            }
        }

        const int row0 = wqlo + (lane >> 2);
        const int row1 = row0 + 8;
        if (k0 + 63 > wqlo) {
            #pragma unroll
            for (int nt = 0; nt < 8; nt++) {
                const int col = k0 + nt * 8 + (lane & 3) * 2;
                if (col     > row0) sacc[nt][0] = -1e30f;
                if (col + 1 > row0) sacc[nt][1] = -1e30f;
                if (col     > row1) sacc[nt][2] = -1e30f;
                if (col + 1 > row1) sacc[nt][3] = -1e30f;
            }
        }

        float mx0 = -1e30f, mx1 = -1e30f;
        #pragma unroll
        for (int nt = 0; nt < 8; nt++) {
            mx0 = fmaxf(mx0, fmaxf(sacc[nt][0], sacc[nt][1]));
            mx1 = fmaxf(mx1, fmaxf(sacc[nt][2], sacc[nt][3]));
        }
        mx0 = fmaxf(mx0, __shfl_xor_sync(0xffffffffu, mx0, 1));
        mx0 = fmaxf(mx0, __shfl_xor_sync(0xffffffffu, mx0, 2));
        mx1 = fmaxf(mx1, __shfl_xor_sync(0xffffffffu, mx1, 1));
        mx1 = fmaxf(mx1, __shfl_xor_sync(0xffffffffu, mx1, 2));

        const float mn0 = fmaxf(m0, mx0), mn1 = fmaxf(m1, mx1);
        const float a0 = exp_approx(m0 - mn0), a1 = exp_approx(m1 - mn1);
        m0 = mn0; m1 = mn1;

        float rs0 = 0.0f, rs1 = 0.0f;
        #pragma unroll
        for (int nt = 0; nt < 8; nt++) {
            float p0 = exp_approx(sacc[nt][0] - mn0);
            float p1 = exp_approx(sacc[nt][1] - mn0);
            float p2 = exp_approx(sacc[nt][2] - mn1);
            float p3 = exp_approx(sacc[nt][3] - mn1);
            sacc[nt][0] = p0; sacc[nt][1] = p1; sacc[nt][2] = p2; sacc[nt][3] = p3;
            rs0 += p0 + p1; rs1 += p2 + p3;
        }
        rs0 += __shfl_xor_sync(0xffffffffu, rs0, 1);
        rs0 += __shfl_xor_sync(0xffffffffu, rs0, 2);
        rs1 += __shfl_xor_sync(0xffffffffu, rs1, 1);
        rs1 += __shfl_xor_sync(0xffffffffu, rs1, 2);
        ln0 = ln0 * a0 + rs0;
        ln1 = ln1 * a1 + rs1;

        #pragma unroll
        for (int nt = 0; nt < 8; nt++) {
            oacc[nt][0] *= a0; oacc[nt][1] *= a0;
            oacc[nt][2] *= a1; oacc[nt][3] *= a1;
        }

        {
            const int rrV0 = (lane & 15);
            const int ccV0 = 8 * (lane >> 4);
            #pragma unroll
            for (int ks = 0; ks < 4; ks++) {
                uint32_t pa[4], pl[4];
                {
                    const float c0 = sacc[2 * ks][0],     c1 = sacc[2 * ks][1];
                    const float c2 = sacc[2 * ks][2],     c3 = sacc[2 * ks][3];
                    const float d0 = sacc[2 * ks + 1][0], d1 = sacc[2 * ks + 1][1];
                    const float d2 = sacc[2 * ks + 1][2], d3 = sacc[2 * ks + 1][3];
                    pa[0] = pack_bf16(c0, c1);
                    pa[1] = pack_bf16(c2, c3);
                    pa[2] = pack_bf16(d0, d1);
                    pa[3] = pack_bf16(d2, d3);
                    __nv_bfloat162 h;
                    h = *(__nv_bfloat162*)&pa[0];
                    pl[0] = pack_bf16(c0 - __bfloat162float(h.x), c1 - __bfloat162float(h.y));
                    h = *(__nv_bfloat162*)&pa[1];
                    pl[1] = pack_bf16(c2 - __bfloat162float(h.x), c3 - __bfloat162float(h.y));
                    h = *(__nv_bfloat162*)&pa[2];
                    pl[2] = pack_bf16(d0 - __bfloat162float(h.x), d1 - __bfloat162float(h.y));
                    h = *(__nv_bfloat162*)&pa[3];
                    pl[3] = pack_bf16(d2 - __bfloat162float(h.x), d3 - __bfloat162float(h.y));
                }
                const int rrV = ks * 16 + rrV0;
                #pragma unroll
                for (int np = 0; np < 4; np++) {
                    uint32_t th[4], tl[4];
                    ldmatrix_x4_trans(th, smem_u32(&sVh[rrV * FP + np * 16 + ccV0]));
                    ldmatrix_x4_trans(tl, smem_u32(&sVl[rrV * FP + np * 16 + ccV0]));
                    mma_bf16(oacc[2 * np],     pa, &th[0]);
                    mma_bf16(oacc[2 * np + 1], pa, &th[2]);
                    mma_bf16(oacc[2 * np],     pa, &tl[0]);
                    mma_bf16(oacc[2 * np + 1], pa, &tl[2]);
                    mma_bf16(oacc[2 * np],     pl, &th[0]);
                    mma_bf16(oacc[2 * np + 1], pl, &th[2]);
                }
            }
        }
    }

    // ---- epilogue: normalize + bf16 hi/lo split into [M,1024] ahi/alo ----
    const float inv0 = 1.0f / ln0;
    const float inv1 = 1.0f / ln1;
    const int b = bh >> 4, h = bh & 15;
    const int row0g = q0 + wid * 16 + (lane >> 2);
    const size_t obase = (size_t)b * AS * AD + (size_t)h * AHD;
    #pragma unroll
    for (int nt = 0; nt < 8; nt++) {
        const int col = nt * 8 + (lane & 3) * 2;
        const float x0 = oacc[nt][0] * inv0, x1 = oacc[nt][1] * inv0;
        const float x2 = oacc[nt][2] * inv1, x3 = oacc[nt][3] * inv1;
        const size_t i0 = obase + (size_t)row0g * AD + col;
        const size_t i1 = obase + (size_t)(row0g + 8) * AD + col;
        __nv_bfloat162 h0, h1, l0, l1;
        h0.x = __float2bfloat16(x0); h0.y = __float2bfloat16(x1);
        h1.x = __float2bfloat16(x2); h1.y = __float2bfloat16(x3);
        l0.x = __float2bfloat16(x0 - __bfloat162float(h0.x));
        l0.y = __float2bfloat16(x1 - __bfloat162float(h0.y));
        l1.x = __float2bfloat16(x2 - __bfloat162float(h1.x));
        l1.y = __float2bfloat16(x3 - __bfloat162float(h1.y));
        *(__nv_bfloat162*)&ahi[i0] = h0;
        *(__nv_bfloat162*)&alo[i0] = l0;
        *(__nv_bfloat162*)&ahi[i1] = h1;
        *(__nv_bfloat162*)&alo[i1] = l1;
    }
}

// ---------------------------------------------------------------------------
// Launch
// ---------------------------------------------------------------------------
extern "C" void kernel_launch(void* const* d_in, const int* in_sizes, int n_in,
                              void* d_out, int out_size)
{
    const float* x  = (const float*)d_in[0];
    const float* wq = (const float*)d_in[1];
    const float* bq = (const float*)d_in[2];
    const float* wk = (const float*)d_in[3];
    const float* bk = (const float*)d_in[4];
    const float* wv = (const float*)d_in[5];
    const float* bv = (const float*)d_in[6];
    const float* wo = (const float*)d_in[7];
    const float* bo = (const float*)d_in[8];
    float* out = (float*)d_out;

    __nv_bfloat16 *xhi, *xlo, *whi, *wlo, *ahi, *alo;
    cudaGetSymbolAddress((void**)&xhi, g_xhi);
    cudaGetSymbolAddress((void**)&xlo, g_xlo);
    cudaGetSymbolAddress((void**)&whi, g_whi);
    cudaGetSymbolAddress((void**)&wlo, g_wlo);
    cudaGetSymbolAddress((void**)&ahi, g_ahi);
    cudaGetSymbolAddress((void**)&alo, g_alo);

    __nv_bfloat16 *qhi, *qlo, *khi, *klo, *vhi, *vlo;
    cudaGetSymbolAddress((void**)&qhi, g_qhi);
    cudaGetSymbolAddress((void**)&qlo, g_qlo);
    cudaGetSymbolAddress((void**)&khi, g_khi);
    cudaGetSymbolAddress((void**)&klo, g_klo);
    cudaGetSymbolAddress((void**)&vhi, g_vhi);
    cudaGetSymbolAddress((void**)&vlo, g_vlo);

    cudaFuncSetAttribute(gemm_mma_kernel,
                         cudaFuncAttributeMaxDynamicSharedMemorySize, GEMM_SMEM);
    cudaFuncSetAttribute(flash_mma_kernel,
                         cudaFuncAttributeMaxDynamicSharedMemorySize, FLASH_SMEM);

    // 1) split x + weights
    {
        const int n4x = AM * AD / 4;
        split_kernel<<<(n4x + 255) / 256, 256>>>(x, xhi, xlo, n4x);
        const int n4w = AD * AD / 4;
        const float* ws[4] = {wq, wk, wv, wo};
        for (int i = 0; i < 4; i++)
            split_kernel<<<(n4w + 255) / 256, 256>>>(ws[i], whi + (size_t)i * AD * AD,
                                                     wlo + (size_t)i * AD * AD, n4w);
    }

    dim3 ggrid(AD / GBN, AM / GBM);

    // 2) Q/K/V projections -> head-major bf16 hi/lo directly (scale into q)
    gemm_mma_kernel<<<ggrid, 256, GEMM_SMEM>>>(
        xhi, xlo, whi + 0 * (size_t)AD * AD, wlo + 0 * (size_t)AD * AD, bq,
        nullptr, qhi, qlo, 1, 0.125f);
    gemm_mma_kernel<<<ggrid, 256, GEMM_SMEM>>>(
        xhi, xlo, whi + 1 * (size_t)AD * AD, wlo + 1 * (size_t)AD * AD, bk,
        nullptr, khi, klo, 1, 1.0f);
    gemm_mma_kernel<<<ggrid, 256, GEMM_SMEM>>>(
        xhi, xlo, whi + 2 * (size_t)AD * AD, wlo + 2 * (size_t)AD * AD, bv,
        nullptr, vhi, vlo, 1, 1.0f);

    // 3) flash attention -> ahi/alo ([M,1024] bf16 hi/lo)
    flash_mma_kernel<<<dim3(AS / 128, AB * AH), 256, FLASH_SMEM>>>(
        qhi, qlo, khi, klo, vhi, vlo, ahi, alo);

    // 4) output projection (fp32 + bias)
    gemm_mma_kernel<<<ggrid, 256, GEMM_SMEM>>>(
        ahi, alo, whi + 3 * (size_t)AD * AD, wlo + 3 * (size_t)AD * AD, bo,
        out, nullptr, nullptr, 0, 1.0f);
}